// round 14
// baseline (speedup 1.0000x reference)
#include <cuda_runtime.h>
#include <cuda_pipeline.h>

typedef unsigned long long u64;

// ---- packed f32x2 helpers (exact IEEE fp32 per lane) ---------------------------
__device__ __forceinline__ u64 pk2(float lo, float hi) {
    u64 r; asm("mov.b64 %0, {%1, %2};" : "=l"(r) : "f"(lo), "f"(hi)); return r;
}
__device__ __forceinline__ void fma2(u64& d, u64 a, u64 b) {
    asm("fma.rn.f32x2 %0, %1, %2, %3;" : "=l"(d) : "l"(a), "l"(b), "l"(d));
}
__device__ __forceinline__ float2 up2(u64 v) {
    float lo, hi; asm("mov.b64 {%0, %1}, %2;" : "=f"(lo), "=f"(hi) : "l"(v));
    return make_float2(lo, hi);
}

// ---------------- scratch (static device globals; no allocation) ----------------
__device__ float g_h1 [16 * 64 * 128 * 128];
__device__ float g_h2 [16 * 128 * 64 * 64];
__device__ float g_h3 [16 * 128 * 64 * 64];
__device__ float g_h3r[16 * 128 * 64 * 64];
__device__ float g_t  [4 * 16 * 32 * 64 * 64];   // 4 ci-quarter partials
__device__ float g_z  [16 * 4096 * 4];
// conv2 weights transposed [ci*16+kh*4+kw][oc]; 3x3 weights Winograd-g-transformed
// to [(ci*3+kh)*4+g][oc] with g = {w0, (w0+w1+w2)/2, (w0-w1+w2)/2, w2}
__device__ float  g_w2t [64 * 4 * 4 * 128];
__device__ float  g_w3g [128 * 3 * 4 * 128];
__device__ float  g_wr1g[128 * 3 * 4 * 32];
__device__ float  g_wr2g[128 * 3 * 4 * 32];
__device__ float4 g_en  [2048];               // pre-normalized codebook

// ------- conv1 (FFMA2 oc-pairs) FUSED with weight preprocessing -----------------
// grid (128, 17): by<16 -> conv1 rows for batch by ; by==16 -> weight prep
__global__ void k_conv1(const float* __restrict__ x, const float* __restrict__ w1,
                        const float* __restrict__ b,
                        const float* __restrict__ w2, const float* __restrict__ w3,
                        const float* __restrict__ r1, const float* __restrict__ r2,
                        const float* __restrict__ cbk) {
    if (blockIdx.y == 16) {
        // ---- weight preprocessing slice: 128 blocks x 128 threads, strided ----
        const int NT = 128 * 128;
        const int base = blockIdx.x * 128 + threadIdx.x;
        for (int i = base; i < 206848; i += NT) {
            if (i < 131072) {                      // conv2 transpose
                const int oc = i >> 10, r = i & 1023;
                g_w2t[r * 128 + oc] = w2[i];
            } else if (i < 131072 + 49152) {       // conv3 g-transform
                const int j = i - 131072;
                const int oc = j / 384, r = j % 384, ci = r / 3, kh = r % 3;
                const float w0 = w3[oc * 1152 + ci * 9 + kh * 3 + 0];
                const float w1v = w3[oc * 1152 + ci * 9 + kh * 3 + 1];
                const float w2v = w3[oc * 1152 + ci * 9 + kh * 3 + 2];
                const int bj = (ci * 3 + kh) * 4 * 128 + oc;
                g_w3g[bj]       = w0;
                g_w3g[bj + 128] = (w0 + w1v + w2v) * 0.5f;
                g_w3g[bj + 256] = (w0 - w1v + w2v) * 0.5f;
                g_w3g[bj + 384] = w2v;
            } else if (i < 131072 + 49152 + 12288) {   // res1 g-transform
                const int j = i - 131072 - 49152;
                const int oc = j / 384, r = j % 384, ci = r / 3, kh = r % 3;
                const float w0 = r1[oc * 1152 + ci * 9 + kh * 3 + 0];
                const float w1v = r1[oc * 1152 + ci * 9 + kh * 3 + 1];
                const float w2v = r1[oc * 1152 + ci * 9 + kh * 3 + 2];
                const int bj = (ci * 3 + kh) * 4 * 32 + oc;
                g_wr1g[bj]      = w0;
                g_wr1g[bj + 32] = (w0 + w1v + w2v) * 0.5f;
                g_wr1g[bj + 64] = (w0 - w1v + w2v) * 0.5f;
                g_wr1g[bj + 96] = w2v;
            } else if (i < 131072 + 49152 + 24576) {   // res2 g-transform
                const int j = i - 131072 - 49152 - 12288;
                const int oc = j / 384, r = j % 384, ci = r / 3, kh = r % 3;
                const float w0 = r2[oc * 1152 + ci * 9 + kh * 3 + 0];
                const float w1v = r2[oc * 1152 + ci * 9 + kh * 3 + 1];
                const float w2v = r2[oc * 1152 + ci * 9 + kh * 3 + 2];
                const int bj = (ci * 3 + kh) * 4 * 32 + oc;
                g_wr2g[bj]      = w0;
                g_wr2g[bj + 32] = (w0 + w1v + w2v) * 0.5f;
                g_wr2g[bj + 64] = (w0 - w1v + w2v) * 0.5f;
                g_wr2g[bj + 96] = w2v;
            } else {                                    // codebook normalize
                const int k = i - 131072 - 49152 - 24576;
                const float4 c = ((const float4*)cbk)[k];
                const float n = sqrtf(c.x * c.x + c.y * c.y + c.z * c.z + c.w * c.w);
                const float inv = 1.f / (n + 1e-12f);
                g_en[k] = make_float4(c.x * inv, c.y * inv, c.z * inv, c.w * inv);
            }
        }
        return;
    }

    // ---- conv1 slice: [16,1,256,256] -> relu -> [16,64,128,128], k4 s2 p1 ----
    const int oy = blockIdx.x, bb = blockIdx.y, ox = threadIdx.x;
    __shared__ __align__(16) float sw[16][64];   // [tap][oc], transposed on load
    __shared__ float sb[64];
    for (int i = threadIdx.x; i < 1024; i += 128) sw[i & 15][i >> 4] = w1[i];
    if (threadIdx.x < 64) sb[threadIdx.x] = b[threadIdx.x];
    __syncthreads();

    const float* xb = x + bb * 256 * 256;
    float iv[16];
#pragma unroll
    for (int kh = 0; kh < 4; kh++) {
        const int iy = 2 * oy - 1 + kh;
#pragma unroll
        for (int kw = 0; kw < 4; kw++) {
            const int ix = 2 * ox - 1 + kw;
            iv[kh * 4 + kw] = (iy >= 0 && iy < 256 && ix >= 0 && ix < 256)
                                  ? xb[iy * 256 + ix] : 0.f;
        }
    }
    u64 acc[32];
#pragma unroll
    for (int j = 0; j < 32; j++) acc[j] = pk2(sb[2 * j], sb[2 * j + 1]);
#pragma unroll
    for (int t = 0; t < 16; t++) {
        const u64 vv = pk2(iv[t], iv[t]);
        const u64* wr = (const u64*)&sw[t][0];
#pragma unroll
        for (int j = 0; j < 32; j++) fma2(acc[j], vv, wr[j]);
    }
    float* ob = g_h1 + bb * 64 * 16384 + oy * 128 + ox;
#pragma unroll
    for (int j = 0; j < 32; j++) {
        const float2 f = up2(acc[j]);
        ob[(2 * j) * 16384]     = fmaxf(f.x, 0.f);
        ob[(2 * j + 1) * 16384] = fmaxf(f.y, 0.f);
    }
}

// ---------------- conv2: k4 s2 p1, FFMA2 over oc pairs --------------------------
__global__ __launch_bounds__(128) void k_conv2(const float* __restrict__ wt,
                                               const float* __restrict__ b) {
    const int oy0 = blockIdx.x * 8, ocb = blockIdx.y * 16, bb = blockIdx.z;
    const int tid = threadIdx.x, txx = tid & 15, tyy = tid >> 4;

    __shared__ __align__(16) float s_in[2][2][18][136];
    __shared__ __align__(16) float s_w [2][2][4][4][16];

    for (int i = tid; i < 2 * 2 * 18; i += 128) {
        const int bf = i / 36, r = i % 36, ci = r / 18, row = r % 18;
        s_in[bf][ci][row][3]   = 0.f;
        s_in[bf][ci][row][132] = 0.f;
    }

    const float* inb = g_h1 + bb * 64 * 16384;

    auto stage = [&](int it, int bf) {
        const int c0 = it * 2;
        for (int i = tid; i < 1152; i += 128) {
            const int ci = i / 576, r = i % 576, row = r / 32, seg = r % 32;
            const int iy = 2 * oy0 - 1 + row;
            float* dst = &s_in[bf][ci][row][4 + seg * 4];
            if (iy >= 0 && iy < 128)
                __pipeline_memcpy_async(dst, inb + (c0 + ci) * 16384 + iy * 128 + seg * 4, 16);
            else
                *(float4*)dst = make_float4(0.f, 0.f, 0.f, 0.f);
        }
        for (int i = tid; i < 128; i += 128) {
            const int row = i >> 2, q = i & 3;
            __pipeline_memcpy_async(&((float*)s_w[bf])[row * 16 + q * 4],
                                    wt + (c0 * 16 + row) * 128 + ocb + q * 4, 16);
        }
    };

    u64 acc[8][4];
#pragma unroll
    for (int j = 0; j < 8; j++) {
        const u64 bv = pk2(b[ocb + 2 * j], b[ocb + 2 * j + 1]);
#pragma unroll
        for (int p = 0; p < 4; p++) acc[j][p] = bv;
    }

    stage(0, 0);
    __pipeline_commit();
    int cur = 0;
    for (int it = 0; it < 32; it++) {
        __pipeline_wait_prior(0);
        __syncthreads();
        if (it + 1 < 32) { stage(it + 1, cur ^ 1); __pipeline_commit(); }
#pragma unroll
        for (int ci = 0; ci < 2; ci++) {
#pragma unroll
            for (int kh = 0; kh < 4; kh++) {
                const float* rp = &s_in[cur][ci][2 * tyy + kh][8 * txx];
                const float4 A = *(const float4*)rp;
                const float4 B = *(const float4*)(rp + 4);
                const float4 C = *(const float4*)(rp + 8);
                const float  D = rp[12];
                u64 bv[10];
                bv[0] = pk2(A.w, A.w); bv[1] = pk2(B.x, B.x);
                bv[2] = pk2(B.y, B.y); bv[3] = pk2(B.z, B.z);
                bv[4] = pk2(B.w, B.w); bv[5] = pk2(C.x, C.x);
                bv[6] = pk2(C.y, C.y); bv[7] = pk2(C.z, C.z);
                bv[8] = pk2(C.w, C.w); bv[9] = pk2(D, D);
#pragma unroll
                for (int kw = 0; kw < 4; kw++) {
                    const u64* wb = (const u64*)&s_w[cur][ci][kh][kw][0];
                    const ulonglong2 W0 = *(const ulonglong2*)wb;
                    const ulonglong2 W1 = *(const ulonglong2*)(wb + 2);
                    const ulonglong2 W2 = *(const ulonglong2*)(wb + 4);
                    const ulonglong2 W3 = *(const ulonglong2*)(wb + 6);
                    const u64 w[8] = {W0.x, W0.y, W1.x, W1.y, W2.x, W2.y, W3.x, W3.y};
#pragma unroll
                    for (int j = 0; j < 8; j++)
#pragma unroll
                        for (int p = 0; p < 4; p++)
                            fma2(acc[j][p], bv[2 * p + kw], w[j]);
                }
            }
        }
        cur ^= 1;
    }
    float* ob = g_h2 + (bb * 128 + ocb) * 4096 + (oy0 + tyy) * 64 + 4 * txx;
#pragma unroll
    for (int j = 0; j < 8; j++) {
        const float2 f0 = up2(acc[j][0]), f1 = up2(acc[j][1]);
        const float2 f2 = up2(acc[j][2]), f3 = up2(acc[j][3]);
        *(float4*)(ob + (2 * j) * 4096) = make_float4(
            fmaxf(f0.x, 0.f), fmaxf(f1.x, 0.f), fmaxf(f2.x, 0.f), fmaxf(f3.x, 0.f));
        *(float4*)(ob + (2 * j + 1) * 4096) = make_float4(
            fmaxf(f0.y, 0.f), fmaxf(f1.y, 0.f), fmaxf(f2.y, 0.f), fmaxf(f3.y, 0.f));
    }
}

// ------- 3x3 s1 p1 conv, Winograd F(2,3) along x, 16oc x 4px (round-11 form) ----
template <bool ADD_BIAS, bool WRITE_RELU>
__global__ __launch_bounds__(128) void k_c3w(
    const float* __restrict__ in, const float* __restrict__ gw,
    const float* __restrict__ bias, float* __restrict__ out,
    float* __restrict__ outr, int COUT, int CIN_TOTAL, int CI_COUNT, int NSPLIT) {
    // grid (8 oy-tiles of 8, COUT/16, 16*NSPLIT)
    const int oy0 = blockIdx.x * 8, ocb = blockIdx.y * 16;
    const int half = blockIdx.z % NSPLIT, bb = blockIdx.z / NSPLIT;
    const int ci0 = half * CI_COUNT;
    const int tid = threadIdx.x, txx = tid & 15, tyy = tid >> 4;

    __shared__ __align__(16) float s_in[2][4][10][72];    // rows oy0-1..+8, cols [4..67]
    __shared__ __align__(16) float s_w [2][4][3][4][16];  // [ci][kh][g][oc16]

    for (int i = tid; i < 2 * 4 * 10; i += 128) {
        const int bf = i / 40, r = i % 40, ci = r / 10, row = r % 10;
        s_in[bf][ci][row][3]  = 0.f;
        s_in[bf][ci][row][68] = 0.f;
    }

    const float* inb = in + bb * CIN_TOTAL * 4096;

    auto stage = [&](int it, int bf) {
        const int c0 = ci0 + it * 4;
        for (int i = tid; i < 640; i += 128) {   // 4ci x 10row x 16 seg
            const int ci = i / 160, r = i % 160, row = r / 16, seg = r % 16;
            const int iy = oy0 - 1 + row;
            float* dst = &s_in[bf][ci][row][4 + seg * 4];
            if (iy >= 0 && iy < 64)
                __pipeline_memcpy_async(dst, inb + (c0 + ci) * 4096 + iy * 64 + seg * 4, 16);
            else
                *(float4*)dst = make_float4(0.f, 0.f, 0.f, 0.f);
        }
        for (int i = tid; i < 192; i += 128) {   // 48 rows (ci*12+kh*4+g) x 4 quads
            const int row = i >> 2, q = i & 3;
            __pipeline_memcpy_async(&((float*)s_w[bf])[row * 16 + q * 4],
                                    gw + (c0 * 12 + row) * COUT + ocb + q * 4, 16);
        }
    };

    u64 acc[8][2][4];   // [oc-pair][px-pair][m-term], zero-init (bias folded at end)
#pragma unroll
    for (int j = 0; j < 8; j++)
#pragma unroll
        for (int p = 0; p < 2; p++)
#pragma unroll
            for (int g = 0; g < 4; g++) acc[j][p][g] = 0ull;

    const int NITER = CI_COUNT / 4;
    stage(0, 0);
    __pipeline_commit();
    int cur = 0;
    for (int it = 0; it < NITER; it++) {
        __pipeline_wait_prior(0);
        __syncthreads();
        if (it + 1 < NITER) { stage(it + 1, cur ^ 1); __pipeline_commit(); }
#pragma unroll
        for (int ci = 0; ci < 4; ci++) {
#pragma unroll
            for (int kh = 0; kh < 3; kh++) {
                const float* rp = &s_in[cur][ci][tyy + kh][4 + 4 * txx];
                const float  dm1 = rp[-1];                 // d[-1]
                const float4 B   = *(const float4*)rp;     // d0..d3
                const float  E   = rp[4];                  // d4
                // F(2,3) input transforms for both px-pairs
                const float a0 = dm1 - B.y, a1 = B.x + B.y, a2 = B.y - B.x, a3 = B.x - B.z;
                const float b0 = B.y - B.w, b1 = B.z + B.w, b2 = B.w - B.z, b3 = B.z - E;
                const u64 T[2][4] = {
                    {pk2(a0, a0), pk2(a1, a1), pk2(a2, a2), pk2(a3, a3)},
                    {pk2(b0, b0), pk2(b1, b1), pk2(b2, b2), pk2(b3, b3)}};
#pragma unroll
                for (int g = 0; g < 4; g++) {
                    const u64* wb = (const u64*)&s_w[cur][ci][kh][g][0];
                    const ulonglong2 W0 = *(const ulonglong2*)wb;
                    const ulonglong2 W1 = *(const ulonglong2*)(wb + 2);
                    const ulonglong2 W2 = *(const ulonglong2*)(wb + 4);
                    const ulonglong2 W3 = *(const ulonglong2*)(wb + 6);
                    const u64 w[8] = {W0.x, W0.y, W1.x, W1.y, W2.x, W2.y, W3.x, W3.y};
#pragma unroll
                    for (int j = 0; j < 8; j++) {
                        fma2(acc[j][0][g], T[0][g], w[j]);
                        fma2(acc[j][1][g], T[1][g], w[j]);
                    }
                }
            }
        }
        cur ^= 1;
    }

    // output transform: y0 = b + m0 + m1 + m2 ; y1 = b + m1 - m2 - m3 (per px-pair)
    const u64 ONE = pk2(1.f, 1.f), NEG = pk2(-1.f, -1.f);
    const int off = ((half * 16 + bb) * COUT + ocb) * 4096 + (oy0 + tyy) * 64 + 4 * txx;
#pragma unroll
    for (int j = 0; j < 8; j++) {
        const float bv0 = ADD_BIAS ? bias[ocb + 2 * j] : 0.f;
        const float bv1 = ADD_BIAS ? bias[ocb + 2 * j + 1] : 0.f;
        float lo[4], hi[4];
#pragma unroll
        for (int p = 0; p < 2; p++) {
            u64 y0 = pk2(bv0, bv1), y1 = pk2(bv0, bv1);
            fma2(y0, acc[j][p][0], ONE); fma2(y0, acc[j][p][1], ONE); fma2(y0, acc[j][p][2], ONE);
            fma2(y1, acc[j][p][1], ONE); fma2(y1, acc[j][p][2], NEG); fma2(y1, acc[j][p][3], NEG);
            const float2 f0 = up2(y0), f1 = up2(y1);
            lo[2 * p] = f0.x; lo[2 * p + 1] = f1.x;
            hi[2 * p] = f0.y; hi[2 * p + 1] = f1.y;
        }
        *(float4*)(out + off + (2 * j) * 4096)     = make_float4(lo[0], lo[1], lo[2], lo[3]);
        *(float4*)(out + off + (2 * j + 1) * 4096) = make_float4(hi[0], hi[1], hi[2], hi[3]);
        if (WRITE_RELU) {
            *(float4*)(outr + off + (2 * j) * 4096) = make_float4(
                fmaxf(lo[0], 0.f), fmaxf(lo[1], 0.f), fmaxf(lo[2], 0.f), fmaxf(lo[3], 0.f));
            *(float4*)(outr + off + (2 * j + 1) * 4096) = make_float4(
                fmaxf(hi[0], 0.f), fmaxf(hi[1], 0.f), fmaxf(hi[2], 0.f), fmaxf(hi[3], 0.f));
        }
    }
}

// ------- residual 1x1 #1 (FFMA2, all 128 oc): h3 += b + W*relu(Σt+bt); h3r ------
__global__ __launch_bounds__(64) void k_res1x1_add(const float* __restrict__ w,
                                                   const float* __restrict__ b,
                                                   const float* __restrict__ bt) {
    // grid (xyg=64, b=16), block 64: one px per thread, ALL 128 oc
    const int xy0 = blockIdx.x * 64, bb = blockIdx.y, tx = threadIdx.x;
    __shared__ float s_t[32][64];
    __shared__ __align__(16) float s_w[32][128];  // [ci][oc]

    const float* t0 = g_t + (0 * 16 + bb) * 32 * 4096 + xy0;
    const float* t1 = g_t + (1 * 16 + bb) * 32 * 4096 + xy0;
    const float* t2 = g_t + (2 * 16 + bb) * 32 * 4096 + xy0;
    const float* t3 = g_t + (3 * 16 + bb) * 32 * 4096 + xy0;
    for (int i = tx; i < 32 * 64; i += 64) {
        const int ci = i / 64, xx = i % 64;
        s_t[ci][xx] = fmaxf(t0[ci * 4096 + xx] + t1[ci * 4096 + xx]
                          + t2[ci * 4096 + xx] + t3[ci * 4096 + xx] + bt[ci], 0.f);
    }
    for (int i = tx; i < 128 * 32; i += 64) {
        const int o = i / 32, ci = i % 32;
        s_w[ci][o] = w[o * 32 + ci];
    }
    __syncthreads();

    u64 acc[64];
#pragma unroll
    for (int j = 0; j < 64; j++) acc[j] = pk2(b[2 * j], b[2 * j + 1]);

#pragma unroll 4
    for (int ci = 0; ci < 32; ci++) {
        const float v = s_t[ci][tx];
        const u64 vv = pk2(v, v);
        const u64* wr = (const u64*)&s_w[ci][0];
#pragma unroll
        for (int j = 0; j < 64; j++) fma2(acc[j], vv, wr[j]);
    }

    float* hb  = g_h3  + bb * 128 * 4096 + xy0 + tx;
    float* hrb = g_h3r + bb * 128 * 4096 + xy0 + tx;
#pragma unroll
    for (int j = 0; j < 64; j++) {
        const float2 f = up2(acc[j]);
        const float h0 = hb[(2 * j) * 4096] + f.x;
        const float h1 = hb[(2 * j + 1) * 4096] + f.y;
        hb[(2 * j) * 4096]      = h0;
        hb[(2 * j + 1) * 4096]  = h1;
        hrb[(2 * j) * 4096]     = fmaxf(h0, 0.f);
        hrb[(2 * j + 1) * 4096] = fmaxf(h1, 0.f);
    }
}

// ------- fused res-block-2 1x1 + pre-VQ: z = Wz*relu(h3 + b + W*relu(t)) + bz ---
__global__ __launch_bounds__(64) void k_res1x1z(const float* __restrict__ w,
                                                const float* __restrict__ b,
                                                const float* __restrict__ bt,
                                                const float* __restrict__ wz,
                                                const float* __restrict__ bz) {
    const int xy0 = blockIdx.x * 64, bb = blockIdx.y, tx = threadIdx.x;
    __shared__ float s_t[32][64];
    __shared__ __align__(16) float s_w [32][128];
    __shared__ __align__(16) float s_wz[128][4];

    const float* t0 = g_t + (0 * 16 + bb) * 32 * 4096 + xy0;
    const float* t1 = g_t + (1 * 16 + bb) * 32 * 4096 + xy0;
    const float* t2 = g_t + (2 * 16 + bb) * 32 * 4096 + xy0;
    const float* t3 = g_t + (3 * 16 + bb) * 32 * 4096 + xy0;
    for (int i = tx; i < 32 * 64; i += 64) {
        const int ci = i / 64, xx = i % 64;
        s_t[ci][xx] = fmaxf(t0[ci * 4096 + xx] + t1[ci * 4096 + xx]
                          + t2[ci * 4096 + xx] + t3[ci * 4096 + xx] + bt[ci], 0.f);
    }
    for (int i = tx; i < 128 * 32; i += 64) {
        const int o = i / 32, ci = i % 32;
        s_w[ci][o] = w[o * 32 + ci];
    }
    for (int i = tx; i < 512; i += 64) s_wz[i & 127][i >> 7] = wz[(i >> 7) * 128 + (i & 127)];
    __syncthreads();

    u64 acc[64];
#pragma unroll
    for (int j = 0; j < 64; j++) acc[j] = pk2(b[2 * j], b[2 * j + 1]);

#pragma unroll 4
    for (int ci = 0; ci < 32; ci++) {
        const float v = s_t[ci][tx];
        const u64 vv = pk2(v, v);
        const u64* wr = (const u64*)&s_w[ci][0];
#pragma unroll
        for (int j = 0; j < 64; j++) fma2(acc[j], vv, wr[j]);
    }

    const float* hb = g_h3 + bb * 128 * 4096 + xy0 + tx;
    u64 a01 = pk2(bz[0], bz[1]), a23 = pk2(bz[2], bz[3]);
#pragma unroll
    for (int j = 0; j < 64; j++) {
        const float2 f = up2(acc[j]);
        const float h0 = fmaxf(hb[(2 * j) * 4096] + f.x, 0.f);
        const float h1 = fmaxf(hb[(2 * j + 1) * 4096] + f.y, 0.f);
        const u64* wr0 = (const u64*)&s_wz[2 * j][0];
        const u64* wr1 = (const u64*)&s_wz[2 * j + 1][0];
        const u64 v0 = pk2(h0, h0), v1 = pk2(h1, h1);
        fma2(a01, v0, wr0[0]); fma2(a23, v0, wr0[1]);
        fma2(a01, v1, wr1[0]); fma2(a23, v1, wr1[1]);
    }
    const float2 f01 = up2(a01), f23 = up2(a23);
    ((float4*)g_z)[bb * 4096 + xy0 + tx] = make_float4(f01.x, f01.y, f23.x, f23.y);
}

// ------- cosine VQ: argmax_k <z, e_k>, e pre-normalized; 2 positions/thread -----
__global__ void k_vq(const float* __restrict__ cb, float* __restrict__ out) {
    // grid (8, 16), block 256
    const int bb = blockIdx.y;
    const int p0 = (blockIdx.x * 256 + threadIdx.x) * 2;
    __shared__ float4 s_en[2048];
    for (int k = threadIdx.x; k < 2048; k += 256) s_en[k] = g_en[k];
    __syncthreads();

    float4 z[2];
#pragma unroll
    for (int q = 0; q < 2; q++) z[q] = ((const float4*)g_z)[bb * 4096 + p0 + q];

    float best[2] = {-1e30f, -1e30f};
    int bi[2] = {0, 0};
#pragma unroll 4
    for (int k = 0; k < 2048; k++) {
        const float4 e = s_en[k];
#pragma unroll
        for (int q = 0; q < 2; q++) {
            const float s = z[q].x * e.x + z[q].y * e.y + z[q].z * e.z + z[q].w * e.w;
            if (s > best[q]) { best[q] = s; bi[q] = k; }  // strict >: first max (JAX)
        }
    }
    const float4 q0 = ((const float4*)cb)[bi[0]];
    const float4 q1 = ((const float4*)cb)[bi[1]];
    float* ob = out + bb * 4 * 4096 + p0;
    *(float2*)(ob)            = make_float2(q0.x, q1.x);
    *(float2*)(ob + 4096)     = make_float2(q0.y, q1.y);
    *(float2*)(ob + 2 * 4096) = make_float2(q0.z, q1.z);
    *(float2*)(ob + 3 * 4096) = make_float2(q0.w, q1.w);
}

// --------------------------------- launcher -------------------------------------
extern "C" void kernel_launch(void* const* d_in, const int* in_sizes, int n_in,
                              void* d_out, int out_size) {
    const float* cond  = (const float*)d_in[0];
    const float* w1    = (const float*)d_in[1];
    const float* b1    = (const float*)d_in[2];
    const float* w2    = (const float*)d_in[3];
    const float* b2    = (const float*)d_in[4];
    const float* w3    = (const float*)d_in[5];
    const float* b3    = (const float*)d_in[6];
    const float* r1w1  = (const float*)d_in[7];
    const float* r1b1  = (const float*)d_in[8];
    const float* r1w2  = (const float*)d_in[9];
    const float* r1b2  = (const float*)d_in[10];
    const float* r2w1  = (const float*)d_in[11];
    const float* r2b1  = (const float*)d_in[12];
    const float* r2w2  = (const float*)d_in[13];
    const float* r2b2  = (const float*)d_in[14];
    const float* wpre  = (const float*)d_in[15];
    const float* bpre  = (const float*)d_in[16];
    const float* cbk   = (const float*)d_in[17];

    float *h2p, *h3p, *h3rp, *tp, *w2tp, *w3gp, *wr1gp, *wr2gp;
    cudaGetSymbolAddress((void**)&h2p,   g_h2);
    cudaGetSymbolAddress((void**)&h3p,   g_h3);
    cudaGetSymbolAddress((void**)&h3rp,  g_h3r);
    cudaGetSymbolAddress((void**)&tp,    g_t);
    cudaGetSymbolAddress((void**)&w2tp,  g_w2t);
    cudaGetSymbolAddress((void**)&w3gp,  g_w3g);
    cudaGetSymbolAddress((void**)&wr1gp, g_wr1g);
    cudaGetSymbolAddress((void**)&wr2gp, g_wr2g);

    // conv1 + weight-prep fused (prep is the 17th y-slice)
    k_conv1<<<dim3(128, 17), 128>>>(cond, w1, b1, w2, w3, r1w1, r2w1, cbk);
    k_conv2<<<dim3(8, 8, 16), 128>>>(w2tp, b2);
    k_c3w<true, true><<<dim3(8, 8, 16), 128>>>(h2p, w3gp, b3, h3p, h3rp, 128, 128, 128, 1);

    k_c3w<false, false><<<dim3(8, 2, 64), 128>>>(h3rp, wr1gp, nullptr, tp, nullptr, 32, 128, 32, 4);
    k_res1x1_add<<<dim3(64, 16), 64>>>(r1w2, r1b2, r1b1);

    k_c3w<false, false><<<dim3(8, 2, 64), 128>>>(h3rp, wr2gp, nullptr, tp, nullptr, 32, 128, 32, 4);
    k_res1x1z<<<dim3(64, 16), 64>>>(r2w2, r2b2, r2b1, wpre, bpre);

    k_vq<<<dim3(8, 16), 256>>>(cbk, (float*)d_out);
}

// round 15
// speedup vs baseline: 1.0372x; 1.0372x over previous
#include <cuda_runtime.h>
#include <cuda_pipeline.h>

typedef unsigned long long u64;

// ---- packed f32x2 helpers (exact IEEE fp32 per lane) ---------------------------
__device__ __forceinline__ u64 pk2(float lo, float hi) {
    u64 r; asm("mov.b64 %0, {%1, %2};" : "=l"(r) : "f"(lo), "f"(hi)); return r;
}
__device__ __forceinline__ void fma2(u64& d, u64 a, u64 b) {
    asm("fma.rn.f32x2 %0, %1, %2, %3;" : "=l"(d) : "l"(a), "l"(b), "l"(d));
}
__device__ __forceinline__ float2 up2(u64 v) {
    float lo, hi; asm("mov.b64 {%0, %1}, %2;" : "=f"(lo), "=f"(hi) : "l"(v));
    return make_float2(lo, hi);
}

// ---------------- scratch (static device globals; no allocation) ----------------
__device__ float g_h1 [16 * 64 * 128 * 128];
__device__ float g_h2 [16 * 128 * 64 * 64];
__device__ float g_h3 [16 * 128 * 64 * 64];
__device__ float g_h3r[16 * 128 * 64 * 64];
__device__ float g_t  [4 * 16 * 32 * 64 * 64];   // 4 ci-quarter partials
__device__ float g_z  [16 * 4096 * 4];
// conv2 weights transposed [ci*16+kh*4+kw][oc]; 3x3 weights Winograd-g-transformed
// to [(ci*3+kh)*4+g][oc] with g = {w0, (w0+w1+w2)/2, (w0-w1+w2)/2, w2}
__device__ float  g_w2t [64 * 4 * 4 * 128];
__device__ float  g_w3g [128 * 3 * 4 * 128];
__device__ float  g_wr1g[128 * 3 * 4 * 32];
__device__ float  g_wr2g[128 * 3 * 4 * 32];
__device__ float4 g_en  [2048];               // pre-normalized codebook

// ------- conv1 (FFMA2 oc-pairs) FUSED with weight preprocessing -----------------
// grid (128, 17): by<16 -> conv1 rows for batch by ; by==16 -> weight prep
__global__ void k_conv1(const float* __restrict__ x, const float* __restrict__ w1,
                        const float* __restrict__ b,
                        const float* __restrict__ w2, const float* __restrict__ w3,
                        const float* __restrict__ r1, const float* __restrict__ r2,
                        const float* __restrict__ cbk) {
    if (blockIdx.y == 16) {
        // ---- weight preprocessing slice: 128 blocks x 128 threads, strided ----
        const int NT = 128 * 128;
        const int base = blockIdx.x * 128 + threadIdx.x;
        for (int i = base; i < 206848; i += NT) {
            if (i < 131072) {                      // conv2 transpose
                const int oc = i >> 10, r = i & 1023;
                g_w2t[r * 128 + oc] = w2[i];
            } else if (i < 131072 + 49152) {       // conv3 g-transform
                const int j = i - 131072;
                const int oc = j / 384, r = j % 384, ci = r / 3, kh = r % 3;
                const float w0 = w3[oc * 1152 + ci * 9 + kh * 3 + 0];
                const float w1v = w3[oc * 1152 + ci * 9 + kh * 3 + 1];
                const float w2v = w3[oc * 1152 + ci * 9 + kh * 3 + 2];
                const int bj = (ci * 3 + kh) * 4 * 128 + oc;
                g_w3g[bj]       = w0;
                g_w3g[bj + 128] = (w0 + w1v + w2v) * 0.5f;
                g_w3g[bj + 256] = (w0 - w1v + w2v) * 0.5f;
                g_w3g[bj + 384] = w2v;
            } else if (i < 131072 + 49152 + 12288) {   // res1 g-transform
                const int j = i - 131072 - 49152;
                const int oc = j / 384, r = j % 384, ci = r / 3, kh = r % 3;
                const float w0 = r1[oc * 1152 + ci * 9 + kh * 3 + 0];
                const float w1v = r1[oc * 1152 + ci * 9 + kh * 3 + 1];
                const float w2v = r1[oc * 1152 + ci * 9 + kh * 3 + 2];
                const int bj = (ci * 3 + kh) * 4 * 32 + oc;
                g_wr1g[bj]      = w0;
                g_wr1g[bj + 32] = (w0 + w1v + w2v) * 0.5f;
                g_wr1g[bj + 64] = (w0 - w1v + w2v) * 0.5f;
                g_wr1g[bj + 96] = w2v;
            } else if (i < 131072 + 49152 + 24576) {   // res2 g-transform
                const int j = i - 131072 - 49152 - 12288;
                const int oc = j / 384, r = j % 384, ci = r / 3, kh = r % 3;
                const float w0 = r2[oc * 1152 + ci * 9 + kh * 3 + 0];
                const float w1v = r2[oc * 1152 + ci * 9 + kh * 3 + 1];
                const float w2v = r2[oc * 1152 + ci * 9 + kh * 3 + 2];
                const int bj = (ci * 3 + kh) * 4 * 32 + oc;
                g_wr2g[bj]      = w0;
                g_wr2g[bj + 32] = (w0 + w1v + w2v) * 0.5f;
                g_wr2g[bj + 64] = (w0 - w1v + w2v) * 0.5f;
                g_wr2g[bj + 96] = w2v;
            } else {                                    // codebook normalize
                const int k = i - 131072 - 49152 - 24576;
                const float4 c = ((const float4*)cbk)[k];
                const float n = sqrtf(c.x * c.x + c.y * c.y + c.z * c.z + c.w * c.w);
                const float inv = 1.f / (n + 1e-12f);
                g_en[k] = make_float4(c.x * inv, c.y * inv, c.z * inv, c.w * inv);
            }
        }
        return;
    }

    // ---- conv1 slice: [16,1,256,256] -> relu -> [16,64,128,128], k4 s2 p1 ----
    const int oy = blockIdx.x, bb = blockIdx.y, ox = threadIdx.x;
    __shared__ __align__(16) float sw[16][64];   // [tap][oc], transposed on load
    __shared__ float sb[64];
    for (int i = threadIdx.x; i < 1024; i += 128) sw[i & 15][i >> 4] = w1[i];
    if (threadIdx.x < 64) sb[threadIdx.x] = b[threadIdx.x];
    __syncthreads();

    const float* xb = x + bb * 256 * 256;
    float iv[16];
#pragma unroll
    for (int kh = 0; kh < 4; kh++) {
        const int iy = 2 * oy - 1 + kh;
#pragma unroll
        for (int kw = 0; kw < 4; kw++) {
            const int ix = 2 * ox - 1 + kw;
            iv[kh * 4 + kw] = (iy >= 0 && iy < 256 && ix >= 0 && ix < 256)
                                  ? xb[iy * 256 + ix] : 0.f;
        }
    }
    u64 acc[32];
#pragma unroll
    for (int j = 0; j < 32; j++) acc[j] = pk2(sb[2 * j], sb[2 * j + 1]);
#pragma unroll
    for (int t = 0; t < 16; t++) {
        const u64 vv = pk2(iv[t], iv[t]);
        const u64* wr = (const u64*)&sw[t][0];
#pragma unroll
        for (int j = 0; j < 32; j++) fma2(acc[j], vv, wr[j]);
    }
    float* ob = g_h1 + bb * 64 * 16384 + oy * 128 + ox;
#pragma unroll
    for (int j = 0; j < 32; j++) {
        const float2 f = up2(acc[j]);
        ob[(2 * j) * 16384]     = fmaxf(f.x, 0.f);
        ob[(2 * j + 1) * 16384] = fmaxf(f.y, 0.f);
    }
}

// ---------------- conv2: k4 s2 p1, FFMA2 over oc pairs --------------------------
__global__ __launch_bounds__(128) void k_conv2(const float* __restrict__ wt,
                                               const float* __restrict__ b) {
    const int oy0 = blockIdx.x * 8, ocb = blockIdx.y * 16, bb = blockIdx.z;
    const int tid = threadIdx.x, txx = tid & 15, tyy = tid >> 4;

    __shared__ __align__(16) float s_in[2][2][18][136];
    __shared__ __align__(16) float s_w [2][2][4][4][16];

    for (int i = tid; i < 2 * 2 * 18; i += 128) {
        const int bf = i / 36, r = i % 36, ci = r / 18, row = r % 18;
        s_in[bf][ci][row][3]   = 0.f;
        s_in[bf][ci][row][132] = 0.f;
    }

    const float* inb = g_h1 + bb * 64 * 16384;

    auto stage = [&](int it, int bf) {
        const int c0 = it * 2;
        for (int i = tid; i < 1152; i += 128) {
            const int ci = i / 576, r = i % 576, row = r / 32, seg = r % 32;
            const int iy = 2 * oy0 - 1 + row;
            float* dst = &s_in[bf][ci][row][4 + seg * 4];
            if (iy >= 0 && iy < 128)
                __pipeline_memcpy_async(dst, inb + (c0 + ci) * 16384 + iy * 128 + seg * 4, 16);
            else
                *(float4*)dst = make_float4(0.f, 0.f, 0.f, 0.f);
        }
        for (int i = tid; i < 128; i += 128) {
            const int row = i >> 2, q = i & 3;
            __pipeline_memcpy_async(&((float*)s_w[bf])[row * 16 + q * 4],
                                    wt + (c0 * 16 + row) * 128 + ocb + q * 4, 16);
        }
    };

    u64 acc[8][4];
#pragma unroll
    for (int j = 0; j < 8; j++) {
        const u64 bv = pk2(b[ocb + 2 * j], b[ocb + 2 * j + 1]);
#pragma unroll
        for (int p = 0; p < 4; p++) acc[j][p] = bv;
    }

    stage(0, 0);
    __pipeline_commit();
    int cur = 0;
    for (int it = 0; it < 32; it++) {
        __pipeline_wait_prior(0);
        __syncthreads();
        if (it + 1 < 32) { stage(it + 1, cur ^ 1); __pipeline_commit(); }
#pragma unroll
        for (int ci = 0; ci < 2; ci++) {
#pragma unroll
            for (int kh = 0; kh < 4; kh++) {
                const float* rp = &s_in[cur][ci][2 * tyy + kh][8 * txx];
                const float4 A = *(const float4*)rp;
                const float4 B = *(const float4*)(rp + 4);
                const float4 C = *(const float4*)(rp + 8);
                const float  D = rp[12];
                u64 bv[10];
                bv[0] = pk2(A.w, A.w); bv[1] = pk2(B.x, B.x);
                bv[2] = pk2(B.y, B.y); bv[3] = pk2(B.z, B.z);
                bv[4] = pk2(B.w, B.w); bv[5] = pk2(C.x, C.x);
                bv[6] = pk2(C.y, C.y); bv[7] = pk2(C.z, C.z);
                bv[8] = pk2(C.w, C.w); bv[9] = pk2(D, D);
#pragma unroll
                for (int kw = 0; kw < 4; kw++) {
                    const u64* wb = (const u64*)&s_w[cur][ci][kh][kw][0];
                    const ulonglong2 W0 = *(const ulonglong2*)wb;
                    const ulonglong2 W1 = *(const ulonglong2*)(wb + 2);
                    const ulonglong2 W2 = *(const ulonglong2*)(wb + 4);
                    const ulonglong2 W3 = *(const ulonglong2*)(wb + 6);
                    const u64 w[8] = {W0.x, W0.y, W1.x, W1.y, W2.x, W2.y, W3.x, W3.y};
#pragma unroll
                    for (int j = 0; j < 8; j++)
#pragma unroll
                        for (int p = 0; p < 4; p++)
                            fma2(acc[j][p], bv[2 * p + kw], w[j]);
                }
            }
        }
        cur ^= 1;
    }
    float* ob = g_h2 + (bb * 128 + ocb) * 4096 + (oy0 + tyy) * 64 + 4 * txx;
#pragma unroll
    for (int j = 0; j < 8; j++) {
        const float2 f0 = up2(acc[j][0]), f1 = up2(acc[j][1]);
        const float2 f2 = up2(acc[j][2]), f3 = up2(acc[j][3]);
        *(float4*)(ob + (2 * j) * 4096) = make_float4(
            fmaxf(f0.x, 0.f), fmaxf(f1.x, 0.f), fmaxf(f2.x, 0.f), fmaxf(f3.x, 0.f));
        *(float4*)(ob + (2 * j + 1) * 4096) = make_float4(
            fmaxf(f0.y, 0.f), fmaxf(f1.y, 0.f), fmaxf(f2.y, 0.f), fmaxf(f3.y, 0.f));
    }
}

// ------- 3x3 s1 p1 conv, Winograd F(2,3) along x, 16oc x 4px (round-11 form) ----
template <bool ADD_BIAS, bool WRITE_RELU>
__global__ __launch_bounds__(128) void k_c3w(
    const float* __restrict__ in, const float* __restrict__ gw,
    const float* __restrict__ bias, float* __restrict__ out,
    float* __restrict__ outr, int COUT, int CIN_TOTAL, int CI_COUNT, int NSPLIT) {
    // grid (8 oy-tiles of 8, COUT/16, 16*NSPLIT)
    const int oy0 = blockIdx.x * 8, ocb = blockIdx.y * 16;
    const int half = blockIdx.z % NSPLIT, bb = blockIdx.z / NSPLIT;
    const int ci0 = half * CI_COUNT;
    const int tid = threadIdx.x, txx = tid & 15, tyy = tid >> 4;

    __shared__ __align__(16) float s_in[2][4][10][72];    // rows oy0-1..+8, cols [4..67]
    __shared__ __align__(16) float s_w [2][4][3][4][16];  // [ci][kh][g][oc16]

    for (int i = tid; i < 2 * 4 * 10; i += 128) {
        const int bf = i / 40, r = i % 40, ci = r / 10, row = r % 10;
        s_in[bf][ci][row][3]  = 0.f;
        s_in[bf][ci][row][68] = 0.f;
    }

    const float* inb = in + bb * CIN_TOTAL * 4096;

    auto stage = [&](int it, int bf) {
        const int c0 = ci0 + it * 4;
        for (int i = tid; i < 640; i += 128) {   // 4ci x 10row x 16 seg
            const int ci = i / 160, r = i % 160, row = r / 16, seg = r % 16;
            const int iy = oy0 - 1 + row;
            float* dst = &s_in[bf][ci][row][4 + seg * 4];
            if (iy >= 0 && iy < 64)
                __pipeline_memcpy_async(dst, inb + (c0 + ci) * 4096 + iy * 64 + seg * 4, 16);
            else
                *(float4*)dst = make_float4(0.f, 0.f, 0.f, 0.f);
        }
        for (int i = tid; i < 192; i += 128) {   // 48 rows (ci*12+kh*4+g) x 4 quads
            const int row = i >> 2, q = i & 3;
            __pipeline_memcpy_async(&((float*)s_w[bf])[row * 16 + q * 4],
                                    gw + (c0 * 12 + row) * COUT + ocb + q * 4, 16);
        }
    };

    u64 acc[8][2][4];   // [oc-pair][px-pair][m-term], zero-init (bias folded at end)
#pragma unroll
    for (int j = 0; j < 8; j++)
#pragma unroll
        for (int p = 0; p < 2; p++)
#pragma unroll
            for (int g = 0; g < 4; g++) acc[j][p][g] = 0ull;

    const int NITER = CI_COUNT / 4;
    stage(0, 0);
    __pipeline_commit();
    int cur = 0;
    for (int it = 0; it < NITER; it++) {
        __pipeline_wait_prior(0);
        __syncthreads();
        if (it + 1 < NITER) { stage(it + 1, cur ^ 1); __pipeline_commit(); }
#pragma unroll
        for (int ci = 0; ci < 4; ci++) {
#pragma unroll
            for (int kh = 0; kh < 3; kh++) {
                const float* rp = &s_in[cur][ci][tyy + kh][4 + 4 * txx];
                const float  dm1 = rp[-1];                 // d[-1]
                const float4 B   = *(const float4*)rp;     // d0..d3
                const float  E   = rp[4];                  // d4
                // F(2,3) input transforms for both px-pairs
                const float a0 = dm1 - B.y, a1 = B.x + B.y, a2 = B.y - B.x, a3 = B.x - B.z;
                const float b0 = B.y - B.w, b1 = B.z + B.w, b2 = B.w - B.z, b3 = B.z - E;
                const u64 T[2][4] = {
                    {pk2(a0, a0), pk2(a1, a1), pk2(a2, a2), pk2(a3, a3)},
                    {pk2(b0, b0), pk2(b1, b1), pk2(b2, b2), pk2(b3, b3)}};
#pragma unroll
                for (int g = 0; g < 4; g++) {
                    const u64* wb = (const u64*)&s_w[cur][ci][kh][g][0];
                    const ulonglong2 W0 = *(const ulonglong2*)wb;
                    const ulonglong2 W1 = *(const ulonglong2*)(wb + 2);
                    const ulonglong2 W2 = *(const ulonglong2*)(wb + 4);
                    const ulonglong2 W3 = *(const ulonglong2*)(wb + 6);
                    const u64 w[8] = {W0.x, W0.y, W1.x, W1.y, W2.x, W2.y, W3.x, W3.y};
#pragma unroll
                    for (int j = 0; j < 8; j++) {
                        fma2(acc[j][0][g], T[0][g], w[j]);
                        fma2(acc[j][1][g], T[1][g], w[j]);
                    }
                }
            }
        }
        cur ^= 1;
    }

    // output transform: y0 = b + m0 + m1 + m2 ; y1 = b + m1 - m2 - m3 (per px-pair)
    const u64 ONE = pk2(1.f, 1.f), NEG = pk2(-1.f, -1.f);
    const int off = ((half * 16 + bb) * COUT + ocb) * 4096 + (oy0 + tyy) * 64 + 4 * txx;
#pragma unroll
    for (int j = 0; j < 8; j++) {
        const float bv0 = ADD_BIAS ? bias[ocb + 2 * j] : 0.f;
        const float bv1 = ADD_BIAS ? bias[ocb + 2 * j + 1] : 0.f;
        float lo[4], hi[4];
#pragma unroll
        for (int p = 0; p < 2; p++) {
            u64 y0 = pk2(bv0, bv1), y1 = pk2(bv0, bv1);
            fma2(y0, acc[j][p][0], ONE); fma2(y0, acc[j][p][1], ONE); fma2(y0, acc[j][p][2], ONE);
            fma2(y1, acc[j][p][1], ONE); fma2(y1, acc[j][p][2], NEG); fma2(y1, acc[j][p][3], NEG);
            const float2 f0 = up2(y0), f1 = up2(y1);
            lo[2 * p] = f0.x; lo[2 * p + 1] = f1.x;
            hi[2 * p] = f0.y; hi[2 * p + 1] = f1.y;
        }
        *(float4*)(out + off + (2 * j) * 4096)     = make_float4(lo[0], lo[1], lo[2], lo[3]);
        *(float4*)(out + off + (2 * j + 1) * 4096) = make_float4(hi[0], hi[1], hi[2], hi[3]);
        if (WRITE_RELU) {
            *(float4*)(outr + off + (2 * j) * 4096) = make_float4(
                fmaxf(lo[0], 0.f), fmaxf(lo[1], 0.f), fmaxf(lo[2], 0.f), fmaxf(lo[3], 0.f));
            *(float4*)(outr + off + (2 * j + 1) * 4096) = make_float4(
                fmaxf(hi[0], 0.f), fmaxf(hi[1], 0.f), fmaxf(hi[2], 0.f), fmaxf(hi[3], 0.f));
        }
    }
}

// ------- residual 1x1 #1 (FFMA2, 2 ocg blocks): h3 += b + W*relu(Σt+bt); h3r ----
__global__ __launch_bounds__(64) void k_res1x1_add(const float* __restrict__ w,
                                                   const float* __restrict__ b,
                                                   const float* __restrict__ bt) {
    const int xy0 = blockIdx.x * 64, ocb = blockIdx.y * 64, bb = blockIdx.z, tx = threadIdx.x;
    __shared__ float s_t[32][64];
    __shared__ __align__(16) float s_w[32][64];

    const float* t0 = g_t + (0 * 16 + bb) * 32 * 4096 + xy0;
    const float* t1 = g_t + (1 * 16 + bb) * 32 * 4096 + xy0;
    const float* t2 = g_t + (2 * 16 + bb) * 32 * 4096 + xy0;
    const float* t3 = g_t + (3 * 16 + bb) * 32 * 4096 + xy0;
    for (int i = tx; i < 32 * 64; i += 64) {
        const int ci = i / 64, xx = i % 64;
        s_t[ci][xx] = fmaxf(t0[ci * 4096 + xx] + t1[ci * 4096 + xx]
                          + t2[ci * 4096 + xx] + t3[ci * 4096 + xx] + bt[ci], 0.f);
    }
    for (int i = tx; i < 64 * 32; i += 64) {
        const int o = i / 32, ci = i % 32;
        s_w[ci][o] = w[(ocb + o) * 32 + ci];
    }
    __syncthreads();

    u64 acc[32];
#pragma unroll
    for (int j = 0; j < 32; j++) acc[j] = pk2(b[ocb + 2 * j], b[ocb + 2 * j + 1]);

#pragma unroll 4
    for (int ci = 0; ci < 32; ci++) {
        const float v = s_t[ci][tx];
        const u64 vv = pk2(v, v);
        const u64* wr = (const u64*)&s_w[ci][0];
#pragma unroll
        for (int j = 0; j < 32; j++) fma2(acc[j], vv, wr[j]);
    }

    float* hb  = g_h3  + (bb * 128 + ocb) * 4096 + xy0 + tx;
    float* hrb = g_h3r + (bb * 128 + ocb) * 4096 + xy0 + tx;
#pragma unroll
    for (int j = 0; j < 32; j++) {
        const float2 f = up2(acc[j]);
        const float h0 = hb[(2 * j) * 4096] + f.x;
        const float h1 = hb[(2 * j + 1) * 4096] + f.y;
        hb[(2 * j) * 4096]      = h0;
        hb[(2 * j + 1) * 4096]  = h1;
        hrb[(2 * j) * 4096]     = fmaxf(h0, 0.f);
        hrb[(2 * j + 1) * 4096] = fmaxf(h1, 0.f);
    }
}

// ------- fused res-block-2 1x1 + pre-VQ: z = Wz*relu(h3 + b + W*relu(t)) + bz ---
__global__ __launch_bounds__(64) void k_res1x1z(const float* __restrict__ w,
                                                const float* __restrict__ b,
                                                const float* __restrict__ bt,
                                                const float* __restrict__ wz,
                                                const float* __restrict__ bz) {
    const int xy0 = blockIdx.x * 64, bb = blockIdx.y, tx = threadIdx.x;
    __shared__ float s_t[32][64];
    __shared__ __align__(16) float s_w [32][128];
    __shared__ __align__(16) float s_wz[128][4];

    const float* t0 = g_t + (0 * 16 + bb) * 32 * 4096 + xy0;
    const float* t1 = g_t + (1 * 16 + bb) * 32 * 4096 + xy0;
    const float* t2 = g_t + (2 * 16 + bb) * 32 * 4096 + xy0;
    const float* t3 = g_t + (3 * 16 + bb) * 32 * 4096 + xy0;
    for (int i = tx; i < 32 * 64; i += 64) {
        const int ci = i / 64, xx = i % 64;
        s_t[ci][xx] = fmaxf(t0[ci * 4096 + xx] + t1[ci * 4096 + xx]
                          + t2[ci * 4096 + xx] + t3[ci * 4096 + xx] + bt[ci], 0.f);
    }
    for (int i = tx; i < 128 * 32; i += 64) {
        const int o = i / 32, ci = i % 32;
        s_w[ci][o] = w[o * 32 + ci];
    }
    for (int i = tx; i < 512; i += 64) s_wz[i & 127][i >> 7] = wz[(i >> 7) * 128 + (i & 127)];
    __syncthreads();

    u64 acc[64];
#pragma unroll
    for (int j = 0; j < 64; j++) acc[j] = pk2(b[2 * j], b[2 * j + 1]);

#pragma unroll 4
    for (int ci = 0; ci < 32; ci++) {
        const float v = s_t[ci][tx];
        const u64 vv = pk2(v, v);
        const u64* wr = (const u64*)&s_w[ci][0];
#pragma unroll
        for (int j = 0; j < 64; j++) fma2(acc[j], vv, wr[j]);
    }

    const float* hb = g_h3 + bb * 128 * 4096 + xy0 + tx;
    u64 a01 = pk2(bz[0], bz[1]), a23 = pk2(bz[2], bz[3]);
#pragma unroll
    for (int j = 0; j < 64; j++) {
        const float2 f = up2(acc[j]);
        const float h0 = fmaxf(hb[(2 * j) * 4096] + f.x, 0.f);
        const float h1 = fmaxf(hb[(2 * j + 1) * 4096] + f.y, 0.f);
        const u64* wr0 = (const u64*)&s_wz[2 * j][0];
        const u64* wr1 = (const u64*)&s_wz[2 * j + 1][0];
        const u64 v0 = pk2(h0, h0), v1 = pk2(h1, h1);
        fma2(a01, v0, wr0[0]); fma2(a23, v0, wr0[1]);
        fma2(a01, v1, wr1[0]); fma2(a23, v1, wr1[1]);
    }
    const float2 f01 = up2(a01), f23 = up2(a23);
    ((float4*)g_z)[bb * 4096 + xy0 + tx] = make_float4(f01.x, f01.y, f23.x, f23.y);
}

// ------- cosine VQ: argmax_k <z, e_k>, e pre-normalized; 1 position/thread ------
__global__ void k_vq(const float* __restrict__ cb, float* __restrict__ out) {
    const int bb = blockIdx.y;
    const int p0 = blockIdx.x * 256 + threadIdx.x;
    __shared__ float4 s_en[2048];
    for (int k = threadIdx.x; k < 2048; k += 256) s_en[k] = g_en[k];
    __syncthreads();

    const float4 z = ((const float4*)g_z)[bb * 4096 + p0];
    float best = -1e30f;
    int bi = 0;
#pragma unroll 8
    for (int k = 0; k < 2048; k++) {
        const float4 e = s_en[k];
        const float s = z.x * e.x + z.y * e.y + z.z * e.z + z.w * e.w;
        if (s > best) { best = s; bi = k; }  // strict >: first max (JAX)
    }
    const float4 q = ((const float4*)cb)[bi];
    float* ob = out + bb * 4 * 4096 + p0;
    ob[0]        = q.x;
    ob[4096]     = q.y;
    ob[2 * 4096] = q.z;
    ob[3 * 4096] = q.w;
}

// --------------------------------- launcher -------------------------------------
extern "C" void kernel_launch(void* const* d_in, const int* in_sizes, int n_in,
                              void* d_out, int out_size) {
    const float* cond  = (const float*)d_in[0];
    const float* w1    = (const float*)d_in[1];
    const float* b1    = (const float*)d_in[2];
    const float* w2    = (const float*)d_in[3];
    const float* b2    = (const float*)d_in[4];
    const float* w3    = (const float*)d_in[5];
    const float* b3    = (const float*)d_in[6];
    const float* r1w1  = (const float*)d_in[7];
    const float* r1b1  = (const float*)d_in[8];
    const float* r1w2  = (const float*)d_in[9];
    const float* r1b2  = (const float*)d_in[10];
    const float* r2w1  = (const float*)d_in[11];
    const float* r2b1  = (const float*)d_in[12];
    const float* r2w2  = (const float*)d_in[13];
    const float* r2b2  = (const float*)d_in[14];
    const float* wpre  = (const float*)d_in[15];
    const float* bpre  = (const float*)d_in[16];
    const float* cbk   = (const float*)d_in[17];

    float *h2p, *h3p, *h3rp, *tp, *w2tp, *w3gp, *wr1gp, *wr2gp;
    cudaGetSymbolAddress((void**)&h2p,   g_h2);
    cudaGetSymbolAddress((void**)&h3p,   g_h3);
    cudaGetSymbolAddress((void**)&h3rp,  g_h3r);
    cudaGetSymbolAddress((void**)&tp,    g_t);
    cudaGetSymbolAddress((void**)&w2tp,  g_w2t);
    cudaGetSymbolAddress((void**)&w3gp,  g_w3g);
    cudaGetSymbolAddress((void**)&wr1gp, g_wr1g);
    cudaGetSymbolAddress((void**)&wr2gp, g_wr2g);

    // conv1 + weight-prep fused (prep is the 17th y-slice)
    k_conv1<<<dim3(128, 17), 128>>>(cond, w1, b1, w2, w3, r1w1, r2w1, cbk);
    k_conv2<<<dim3(8, 8, 16), 128>>>(w2tp, b2);
    k_c3w<true, true><<<dim3(8, 8, 16), 128>>>(h2p, w3gp, b3, h3p, h3rp, 128, 128, 128, 1);

    k_c3w<false, false><<<dim3(8, 2, 64), 128>>>(h3rp, wr1gp, nullptr, tp, nullptr, 32, 128, 32, 4);
    k_res1x1_add<<<dim3(64, 2, 16), 64>>>(r1w2, r1b2, r1b1);

    k_c3w<false, false><<<dim3(8, 2, 64), 128>>>(h3rp, wr2gp, nullptr, tp, nullptr, 32, 128, 32, 4);
    k_res1x1z<<<dim3(64, 16), 64>>>(r2w2, r2b2, r2b1, wpre, bpre);

    k_vq<<<dim3(16, 16), 256>>>(cbk, (float*)d_out);
}

// round 16
// speedup vs baseline: 1.0852x; 1.0463x over previous
#include <cuda_runtime.h>
#include <cuda_pipeline.h>

typedef unsigned long long u64;

// ---- packed f32x2 helpers (exact IEEE fp32 per lane) ---------------------------
__device__ __forceinline__ u64 pk2(float lo, float hi) {
    u64 r; asm("mov.b64 %0, {%1, %2};" : "=l"(r) : "f"(lo), "f"(hi)); return r;
}
__device__ __forceinline__ void fma2(u64& d, u64 a, u64 b) {
    asm("fma.rn.f32x2 %0, %1, %2, %3;" : "=l"(d) : "l"(a), "l"(b), "l"(d));
}
__device__ __forceinline__ float2 up2(u64 v) {
    float lo, hi; asm("mov.b64 {%0, %1}, %2;" : "=f"(lo), "=f"(hi) : "l"(v));
    return make_float2(lo, hi);
}

// ---------------- scratch (static device globals; no allocation) ----------------
__device__ float g_h1 [16 * 64 * 128 * 128];
__device__ float g_h2 [16 * 128 * 64 * 64];
__device__ float g_h3 [16 * 128 * 64 * 64];      // raw; res convs relu on load
__device__ float g_t  [4 * 16 * 32 * 64 * 64];   // 4 ci-quarter partials
__device__ float g_z  [16 * 4096 * 4];
// conv2 weights transposed [ci*16+kh*4+kw][oc]; 3x3 weights Winograd-g-transformed
// to [(ci*3+kh)*4+g][oc] with g = {w0, (w0+w1+w2)/2, (w0-w1+w2)/2, w2}
__device__ float  g_w2t [64 * 4 * 4 * 128];
__device__ float  g_w3g [128 * 3 * 4 * 128];
__device__ float  g_wr1g[128 * 3 * 4 * 32];
__device__ float  g_wr2g[128 * 3 * 4 * 32];
__device__ float4 g_en  [2048];               // pre-normalized codebook

// ------- conv1 (FFMA2 oc-pairs) FUSED with weight preprocessing -----------------
// grid (128, 17): by<16 -> conv1 rows for batch by ; by==16 -> weight prep
__global__ void k_conv1(const float* __restrict__ x, const float* __restrict__ w1,
                        const float* __restrict__ b,
                        const float* __restrict__ w2, const float* __restrict__ w3,
                        const float* __restrict__ r1, const float* __restrict__ r2,
                        const float* __restrict__ cbk) {
    if (blockIdx.y == 16) {
        const int NT = 128 * 128;
        const int base = blockIdx.x * 128 + threadIdx.x;
        for (int i = base; i < 206848; i += NT) {
            if (i < 131072) {                      // conv2 transpose
                const int oc = i >> 10, r = i & 1023;
                g_w2t[r * 128 + oc] = w2[i];
            } else if (i < 131072 + 49152) {       // conv3 g-transform
                const int j = i - 131072;
                const int oc = j / 384, r = j % 384, ci = r / 3, kh = r % 3;
                const float w0 = w3[oc * 1152 + ci * 9 + kh * 3 + 0];
                const float w1v = w3[oc * 1152 + ci * 9 + kh * 3 + 1];
                const float w2v = w3[oc * 1152 + ci * 9 + kh * 3 + 2];
                const int bj = (ci * 3 + kh) * 4 * 128 + oc;
                g_w3g[bj]       = w0;
                g_w3g[bj + 128] = (w0 + w1v + w2v) * 0.5f;
                g_w3g[bj + 256] = (w0 - w1v + w2v) * 0.5f;
                g_w3g[bj + 384] = w2v;
            } else if (i < 131072 + 49152 + 12288) {   // res1 g-transform
                const int j = i - 131072 - 49152;
                const int oc = j / 384, r = j % 384, ci = r / 3, kh = r % 3;
                const float w0 = r1[oc * 1152 + ci * 9 + kh * 3 + 0];
                const float w1v = r1[oc * 1152 + ci * 9 + kh * 3 + 1];
                const float w2v = r1[oc * 1152 + ci * 9 + kh * 3 + 2];
                const int bj = (ci * 3 + kh) * 4 * 32 + oc;
                g_wr1g[bj]      = w0;
                g_wr1g[bj + 32] = (w0 + w1v + w2v) * 0.5f;
                g_wr1g[bj + 64] = (w0 - w1v + w2v) * 0.5f;
                g_wr1g[bj + 96] = w2v;
            } else if (i < 131072 + 49152 + 24576) {   // res2 g-transform
                const int j = i - 131072 - 49152 - 12288;
                const int oc = j / 384, r = j % 384, ci = r / 3, kh = r % 3;
                const float w0 = r2[oc * 1152 + ci * 9 + kh * 3 + 0];
                const float w1v = r2[oc * 1152 + ci * 9 + kh * 3 + 1];
                const float w2v = r2[oc * 1152 + ci * 9 + kh * 3 + 2];
                const int bj = (ci * 3 + kh) * 4 * 32 + oc;
                g_wr2g[bj]      = w0;
                g_wr2g[bj + 32] = (w0 + w1v + w2v) * 0.5f;
                g_wr2g[bj + 64] = (w0 - w1v + w2v) * 0.5f;
                g_wr2g[bj + 96] = w2v;
            } else {                                    // codebook normalize
                const int k = i - 131072 - 49152 - 24576;
                const float4 c = ((const float4*)cbk)[k];
                const float n = sqrtf(c.x * c.x + c.y * c.y + c.z * c.z + c.w * c.w);
                const float inv = 1.f / (n + 1e-12f);
                g_en[k] = make_float4(c.x * inv, c.y * inv, c.z * inv, c.w * inv);
            }
        }
        return;
    }

    // ---- conv1 slice: [16,1,256,256] -> relu -> [16,64,128,128], k4 s2 p1 ----
    const int oy = blockIdx.x, bb = blockIdx.y, ox = threadIdx.x;
    __shared__ __align__(16) float sw[16][64];   // [tap][oc], transposed on load
    __shared__ float sb[64];
    for (int i = threadIdx.x; i < 1024; i += 128) sw[i & 15][i >> 4] = w1[i];
    if (threadIdx.x < 64) sb[threadIdx.x] = b[threadIdx.x];
    __syncthreads();

    const float* xb = x + bb * 256 * 256;
    float iv[16];
#pragma unroll
    for (int kh = 0; kh < 4; kh++) {
        const int iy = 2 * oy - 1 + kh;
#pragma unroll
        for (int kw = 0; kw < 4; kw++) {
            const int ix = 2 * ox - 1 + kw;
            iv[kh * 4 + kw] = (iy >= 0 && iy < 256 && ix >= 0 && ix < 256)
                                  ? xb[iy * 256 + ix] : 0.f;
        }
    }
    u64 acc[32];
#pragma unroll
    for (int j = 0; j < 32; j++) acc[j] = pk2(sb[2 * j], sb[2 * j + 1]);
#pragma unroll
    for (int t = 0; t < 16; t++) {
        const u64 vv = pk2(iv[t], iv[t]);
        const u64* wr = (const u64*)&sw[t][0];
#pragma unroll
        for (int j = 0; j < 32; j++) fma2(acc[j], vv, wr[j]);
    }
    float* ob = g_h1 + bb * 64 * 16384 + oy * 128 + ox;
#pragma unroll
    for (int j = 0; j < 32; j++) {
        const float2 f = up2(acc[j]);
        ob[(2 * j) * 16384]     = fmaxf(f.x, 0.f);
        ob[(2 * j + 1) * 16384] = fmaxf(f.y, 0.f);
    }
}

// ---------------- conv2: k4 s2 p1, FFMA2 over oc pairs --------------------------
__global__ __launch_bounds__(128) void k_conv2(const float* __restrict__ wt,
                                               const float* __restrict__ b) {
    const int oy0 = blockIdx.x * 8, ocb = blockIdx.y * 16, bb = blockIdx.z;
    const int tid = threadIdx.x, txx = tid & 15, tyy = tid >> 4;

    __shared__ __align__(16) float s_in[2][2][18][136];
    __shared__ __align__(16) float s_w [2][2][4][4][16];

    for (int i = tid; i < 2 * 2 * 18; i += 128) {
        const int bf = i / 36, r = i % 36, ci = r / 18, row = r % 18;
        s_in[bf][ci][row][3]   = 0.f;
        s_in[bf][ci][row][132] = 0.f;
    }

    const float* inb = g_h1 + bb * 64 * 16384;

    auto stage = [&](int it, int bf) {
        const int c0 = it * 2;
        for (int i = tid; i < 1152; i += 128) {
            const int ci = i / 576, r = i % 576, row = r / 32, seg = r % 32;
            const int iy = 2 * oy0 - 1 + row;
            float* dst = &s_in[bf][ci][row][4 + seg * 4];
            if (iy >= 0 && iy < 128)
                __pipeline_memcpy_async(dst, inb + (c0 + ci) * 16384 + iy * 128 + seg * 4, 16);
            else
                *(float4*)dst = make_float4(0.f, 0.f, 0.f, 0.f);
        }
        for (int i = tid; i < 128; i += 128) {
            const int row = i >> 2, q = i & 3;
            __pipeline_memcpy_async(&((float*)s_w[bf])[row * 16 + q * 4],
                                    wt + (c0 * 16 + row) * 128 + ocb + q * 4, 16);
        }
    };

    u64 acc[8][4];
#pragma unroll
    for (int j = 0; j < 8; j++) {
        const u64 bv = pk2(b[ocb + 2 * j], b[ocb + 2 * j + 1]);
#pragma unroll
        for (int p = 0; p < 4; p++) acc[j][p] = bv;
    }

    stage(0, 0);
    __pipeline_commit();
    int cur = 0;
    for (int it = 0; it < 32; it++) {
        __pipeline_wait_prior(0);
        __syncthreads();
        if (it + 1 < 32) { stage(it + 1, cur ^ 1); __pipeline_commit(); }
#pragma unroll
        for (int ci = 0; ci < 2; ci++) {
#pragma unroll
            for (int kh = 0; kh < 4; kh++) {
                const float* rp = &s_in[cur][ci][2 * tyy + kh][8 * txx];
                const float4 A = *(const float4*)rp;
                const float4 B = *(const float4*)(rp + 4);
                const float4 C = *(const float4*)(rp + 8);
                const float  D = rp[12];
                u64 bv[10];
                bv[0] = pk2(A.w, A.w); bv[1] = pk2(B.x, B.x);
                bv[2] = pk2(B.y, B.y); bv[3] = pk2(B.z, B.z);
                bv[4] = pk2(B.w, B.w); bv[5] = pk2(C.x, C.x);
                bv[6] = pk2(C.y, C.y); bv[7] = pk2(C.z, C.z);
                bv[8] = pk2(C.w, C.w); bv[9] = pk2(D, D);
#pragma unroll
                for (int kw = 0; kw < 4; kw++) {
                    const u64* wb = (const u64*)&s_w[cur][ci][kh][kw][0];
                    const ulonglong2 W0 = *(const ulonglong2*)wb;
                    const ulonglong2 W1 = *(const ulonglong2*)(wb + 2);
                    const ulonglong2 W2 = *(const ulonglong2*)(wb + 4);
                    const ulonglong2 W3 = *(const ulonglong2*)(wb + 6);
                    const u64 w[8] = {W0.x, W0.y, W1.x, W1.y, W2.x, W2.y, W3.x, W3.y};
#pragma unroll
                    for (int j = 0; j < 8; j++)
#pragma unroll
                        for (int p = 0; p < 4; p++)
                            fma2(acc[j][p], bv[2 * p + kw], w[j]);
                }
            }
        }
        cur ^= 1;
    }
    float* ob = g_h2 + (bb * 128 + ocb) * 4096 + (oy0 + tyy) * 64 + 4 * txx;
#pragma unroll
    for (int j = 0; j < 8; j++) {
        const float2 f0 = up2(acc[j][0]), f1 = up2(acc[j][1]);
        const float2 f2 = up2(acc[j][2]), f3 = up2(acc[j][3]);
        *(float4*)(ob + (2 * j) * 4096) = make_float4(
            fmaxf(f0.x, 0.f), fmaxf(f1.x, 0.f), fmaxf(f2.x, 0.f), fmaxf(f3.x, 0.f));
        *(float4*)(ob + (2 * j + 1) * 4096) = make_float4(
            fmaxf(f0.y, 0.f), fmaxf(f1.y, 0.f), fmaxf(f2.y, 0.f), fmaxf(f3.y, 0.f));
    }
}

// ------- 3x3 s1 p1 conv, Winograd F(2,3) along x, 16oc x 4px --------------------
// RELU_IN: apply relu to staged inputs in the compute loop (FMNMX rides alu pipe)
template <bool ADD_BIAS, bool RELU_IN>
__global__ __launch_bounds__(128) void k_c3w(
    const float* __restrict__ in, const float* __restrict__ gw,
    const float* __restrict__ bias, float* __restrict__ out,
    int COUT, int CIN_TOTAL, int CI_COUNT, int NSPLIT) {
    // grid (8 oy-tiles of 8, COUT/16, 16*NSPLIT)
    const int oy0 = blockIdx.x * 8, ocb = blockIdx.y * 16;
    const int half = blockIdx.z % NSPLIT, bb = blockIdx.z / NSPLIT;
    const int ci0 = half * CI_COUNT;
    const int tid = threadIdx.x, txx = tid & 15, tyy = tid >> 4;

    __shared__ __align__(16) float s_in[2][4][10][72];    // rows oy0-1..+8, cols [4..67]
    __shared__ __align__(16) float s_w [2][4][3][4][16];  // [ci][kh][g][oc16]

    for (int i = tid; i < 2 * 4 * 10; i += 128) {
        const int bf = i / 40, r = i % 40, ci = r / 10, row = r % 10;
        s_in[bf][ci][row][3]  = 0.f;
        s_in[bf][ci][row][68] = 0.f;
    }

    const float* inb = in + bb * CIN_TOTAL * 4096;

    auto stage = [&](int it, int bf) {
        const int c0 = ci0 + it * 4;
        for (int i = tid; i < 640; i += 128) {   // 4ci x 10row x 16 seg
            const int ci = i / 160, r = i % 160, row = r / 16, seg = r % 16;
            const int iy = oy0 - 1 + row;
            float* dst = &s_in[bf][ci][row][4 + seg * 4];
            if (iy >= 0 && iy < 64)
                __pipeline_memcpy_async(dst, inb + (c0 + ci) * 4096 + iy * 64 + seg * 4, 16);
            else
                *(float4*)dst = make_float4(0.f, 0.f, 0.f, 0.f);
        }
        for (int i = tid; i < 192; i += 128) {   // 48 rows (ci*12+kh*4+g) x 4 quads
            const int row = i >> 2, q = i & 3;
            __pipeline_memcpy_async(&((float*)s_w[bf])[row * 16 + q * 4],
                                    gw + (c0 * 12 + row) * COUT + ocb + q * 4, 16);
        }
    };

    u64 acc[8][2][4];   // [oc-pair][px-pair][m-term], zero-init (bias folded at end)
#pragma unroll
    for (int j = 0; j < 8; j++)
#pragma unroll
        for (int p = 0; p < 2; p++)
#pragma unroll
            for (int g = 0; g < 4; g++) acc[j][p][g] = 0ull;

    const int NITER = CI_COUNT / 4;
    stage(0, 0);
    __pipeline_commit();
    int cur = 0;
    for (int it = 0; it < NITER; it++) {
        __pipeline_wait_prior(0);
        __syncthreads();
        if (it + 1 < NITER) { stage(it + 1, cur ^ 1); __pipeline_commit(); }
#pragma unroll
        for (int ci = 0; ci < 4; ci++) {
#pragma unroll
            for (int kh = 0; kh < 3; kh++) {
                const float* rp = &s_in[cur][ci][tyy + kh][4 + 4 * txx];
                float  dm1 = rp[-1];                 // d[-1]
                float4 B   = *(const float4*)rp;     // d0..d3
                float  E   = rp[4];                  // d4
                if (RELU_IN) {
                    dm1 = fmaxf(dm1, 0.f);
                    B.x = fmaxf(B.x, 0.f); B.y = fmaxf(B.y, 0.f);
                    B.z = fmaxf(B.z, 0.f); B.w = fmaxf(B.w, 0.f);
                    E   = fmaxf(E, 0.f);
                }
                // F(2,3) input transforms for both px-pairs
                const float a0 = dm1 - B.y, a1 = B.x + B.y, a2 = B.y - B.x, a3 = B.x - B.z;
                const float b0 = B.y - B.w, b1 = B.z + B.w, b2 = B.w - B.z, b3 = B.z - E;
                const u64 T[2][4] = {
                    {pk2(a0, a0), pk2(a1, a1), pk2(a2, a2), pk2(a3, a3)},
                    {pk2(b0, b0), pk2(b1, b1), pk2(b2, b2), pk2(b3, b3)}};
#pragma unroll
                for (int g = 0; g < 4; g++) {
                    const u64* wb = (const u64*)&s_w[cur][ci][kh][g][0];
                    const ulonglong2 W0 = *(const ulonglong2*)wb;
                    const ulonglong2 W1 = *(const ulonglong2*)(wb + 2);
                    const ulonglong2 W2 = *(const ulonglong2*)(wb + 4);
                    const ulonglong2 W3 = *(const ulonglong2*)(wb + 6);
                    const u64 w[8] = {W0.x, W0.y, W1.x, W1.y, W2.x, W2.y, W3.x, W3.y};
#pragma unroll
                    for (int j = 0; j < 8; j++) {
                        fma2(acc[j][0][g], T[0][g], w[j]);
                        fma2(acc[j][1][g], T[1][g], w[j]);
                    }
                }
            }
        }
        cur ^= 1;
    }

    // output transform: y0 = b + m0 + m1 + m2 ; y1 = b + m1 - m2 - m3 (per px-pair)
    const u64 ONE = pk2(1.f, 1.f), NEG = pk2(-1.f, -1.f);
    const int off = ((half * 16 + bb) * COUT + ocb) * 4096 + (oy0 + tyy) * 64 + 4 * txx;
#pragma unroll
    for (int j = 0; j < 8; j++) {
        const float bv0 = ADD_BIAS ? bias[ocb + 2 * j] : 0.f;
        const float bv1 = ADD_BIAS ? bias[ocb + 2 * j + 1] : 0.f;
        float lo[4], hi[4];
#pragma unroll
        for (int p = 0; p < 2; p++) {
            u64 y0 = pk2(bv0, bv1), y1 = pk2(bv0, bv1);
            fma2(y0, acc[j][p][0], ONE); fma2(y0, acc[j][p][1], ONE); fma2(y0, acc[j][p][2], ONE);
            fma2(y1, acc[j][p][1], ONE); fma2(y1, acc[j][p][2], NEG); fma2(y1, acc[j][p][3], NEG);
            const float2 f0 = up2(y0), f1 = up2(y1);
            lo[2 * p] = f0.x; lo[2 * p + 1] = f1.x;
            hi[2 * p] = f0.y; hi[2 * p + 1] = f1.y;
        }
        *(float4*)(out + off + (2 * j) * 4096)     = make_float4(lo[0], lo[1], lo[2], lo[3]);
        *(float4*)(out + off + (2 * j + 1) * 4096) = make_float4(hi[0], hi[1], hi[2], hi[3]);
    }
}

// ------- residual 1x1 #1 (FFMA2, 2 ocg blocks): h3 += b + W*relu(Σt+bt) ---------
__global__ __launch_bounds__(64) void k_res1x1_add(const float* __restrict__ w,
                                                   const float* __restrict__ b,
                                                   const float* __restrict__ bt) {
    const int xy0 = blockIdx.x * 64, ocb = blockIdx.y * 64, bb = blockIdx.z, tx = threadIdx.x;
    __shared__ float s_t[32][64];
    __shared__ __align__(16) float s_w[32][64];

    const float* t0 = g_t + (0 * 16 + bb) * 32 * 4096 + xy0;
    const float* t1 = g_t + (1 * 16 + bb) * 32 * 4096 + xy0;
    const float* t2 = g_t + (2 * 16 + bb) * 32 * 4096 + xy0;
    const float* t3 = g_t + (3 * 16 + bb) * 32 * 4096 + xy0;
    for (int i = tx; i < 32 * 64; i += 64) {
        const int ci = i / 64, xx = i % 64;
        s_t[ci][xx] = fmaxf(t0[ci * 4096 + xx] + t1[ci * 4096 + xx]
                          + t2[ci * 4096 + xx] + t3[ci * 4096 + xx] + bt[ci], 0.f);
    }
    for (int i = tx; i < 64 * 32; i += 64) {
        const int o = i / 32, ci = i % 32;
        s_w[ci][o] = w[(ocb + o) * 32 + ci];
    }
    __syncthreads();

    u64 acc[32];
#pragma unroll
    for (int j = 0; j < 32; j++) acc[j] = pk2(b[ocb + 2 * j], b[ocb + 2 * j + 1]);

#pragma unroll 4
    for (int ci = 0; ci < 32; ci++) {
        const float v = s_t[ci][tx];
        const u64 vv = pk2(v, v);
        const u64* wr = (const u64*)&s_w[ci][0];
#pragma unroll
        for (int j = 0; j < 32; j++) fma2(acc[j], vv, wr[j]);
    }

    float* hb = g_h3 + (bb * 128 + ocb) * 4096 + xy0 + tx;
#pragma unroll
    for (int j = 0; j < 32; j++) {
        const float2 f = up2(acc[j]);
        hb[(2 * j) * 4096]     += f.x;
        hb[(2 * j + 1) * 4096] += f.y;
    }
}

// ------- fused res-block-2 1x1 + pre-VQ: z = Wz*relu(h3 + b + W*relu(t)) + bz ---
__global__ __launch_bounds__(64) void k_res1x1z(const float* __restrict__ w,
                                                const float* __restrict__ b,
                                                const float* __restrict__ bt,
                                                const float* __restrict__ wz,
                                                const float* __restrict__ bz) {
    const int xy0 = blockIdx.x * 64, bb = blockIdx.y, tx = threadIdx.x;
    __shared__ float s_t[32][64];
    __shared__ __align__(16) float s_w [32][128];
    __shared__ __align__(16) float s_wz[128][4];

    const float* t0 = g_t + (0 * 16 + bb) * 32 * 4096 + xy0;
    const float* t1 = g_t + (1 * 16 + bb) * 32 * 4096 + xy0;
    const float* t2 = g_t + (2 * 16 + bb) * 32 * 4096 + xy0;
    const float* t3 = g_t + (3 * 16 + bb) * 32 * 4096 + xy0;
    for (int i = tx; i < 32 * 64; i += 64) {
        const int ci = i / 64, xx = i % 64;
        s_t[ci][xx] = fmaxf(t0[ci * 4096 + xx] + t1[ci * 4096 + xx]
                          + t2[ci * 4096 + xx] + t3[ci * 4096 + xx] + bt[ci], 0.f);
    }
    for (int i = tx; i < 128 * 32; i += 64) {
        const int o = i / 32, ci = i % 32;
        s_w[ci][o] = w[o * 32 + ci];
    }
    for (int i = tx; i < 512; i += 64) s_wz[i & 127][i >> 7] = wz[(i >> 7) * 128 + (i & 127)];
    __syncthreads();

    u64 acc[64];
#pragma unroll
    for (int j = 0; j < 64; j++) acc[j] = pk2(b[2 * j], b[2 * j + 1]);

#pragma unroll 4
    for (int ci = 0; ci < 32; ci++) {
        const float v = s_t[ci][tx];
        const u64 vv = pk2(v, v);
        const u64* wr = (const u64*)&s_w[ci][0];
#pragma unroll
        for (int j = 0; j < 64; j++) fma2(acc[j], vv, wr[j]);
    }

    const float* hb = g_h3 + bb * 128 * 4096 + xy0 + tx;
    u64 a01 = pk2(bz[0], bz[1]), a23 = pk2(bz[2], bz[3]);
#pragma unroll
    for (int j = 0; j < 64; j++) {
        const float2 f = up2(acc[j]);
        const float h0 = fmaxf(hb[(2 * j) * 4096] + f.x, 0.f);
        const float h1 = fmaxf(hb[(2 * j + 1) * 4096] + f.y, 0.f);
        const u64* wr0 = (const u64*)&s_wz[2 * j][0];
        const u64* wr1 = (const u64*)&s_wz[2 * j + 1][0];
        const u64 v0 = pk2(h0, h0), v1 = pk2(h1, h1);
        fma2(a01, v0, wr0[0]); fma2(a23, v0, wr0[1]);
        fma2(a01, v1, wr1[0]); fma2(a23, v1, wr1[1]);
    }
    const float2 f01 = up2(a01), f23 = up2(a23);
    ((float4*)g_z)[bb * 4096 + xy0 + tx] = make_float4(f01.x, f01.y, f23.x, f23.y);
}

// ------- cosine VQ: argmax_k <z, e_k>, e pre-normalized; 1 position/thread ------
__global__ void k_vq(const float* __restrict__ cb, float* __restrict__ out) {
    const int bb = blockIdx.y;
    const int p0 = blockIdx.x * 256 + threadIdx.x;
    __shared__ float4 s_en[2048];
    for (int k = threadIdx.x; k < 2048; k += 256) s_en[k] = g_en[k];
    __syncthreads();

    const float4 z = ((const float4*)g_z)[bb * 4096 + p0];
    float best = -1e30f;
    int bi = 0;
#pragma unroll 8
    for (int k = 0; k < 2048; k++) {
        const float4 e = s_en[k];
        const float s = z.x * e.x + z.y * e.y + z.z * e.z + z.w * e.w;
        if (s > best) { best = s; bi = k; }  // strict >: first max (JAX)
    }
    const float4 q = ((const float4*)cb)[bi];
    float* ob = out + bb * 4 * 4096 + p0;
    ob[0]        = q.x;
    ob[4096]     = q.y;
    ob[2 * 4096] = q.z;
    ob[3 * 4096] = q.w;
}

// --------------------------------- launcher -------------------------------------
extern "C" void kernel_launch(void* const* d_in, const int* in_sizes, int n_in,
                              void* d_out, int out_size) {
    const float* cond  = (const float*)d_in[0];
    const float* w1    = (const float*)d_in[1];
    const float* b1    = (const float*)d_in[2];
    const float* w2    = (const float*)d_in[3];
    const float* b2    = (const float*)d_in[4];
    const float* w3    = (const float*)d_in[5];
    const float* b3    = (const float*)d_in[6];
    const float* r1w1  = (const float*)d_in[7];
    const float* r1b1  = (const float*)d_in[8];
    const float* r1w2  = (const float*)d_in[9];
    const float* r1b2  = (const float*)d_in[10];
    const float* r2w1  = (const float*)d_in[11];
    const float* r2b1  = (const float*)d_in[12];
    const float* r2w2  = (const float*)d_in[13];
    const float* r2b2  = (const float*)d_in[14];
    const float* wpre  = (const float*)d_in[15];
    const float* bpre  = (const float*)d_in[16];
    const float* cbk   = (const float*)d_in[17];

    float *h2p, *h3p, *tp, *w2tp, *w3gp, *wr1gp, *wr2gp;
    cudaGetSymbolAddress((void**)&h2p,   g_h2);
    cudaGetSymbolAddress((void**)&h3p,   g_h3);
    cudaGetSymbolAddress((void**)&tp,    g_t);
    cudaGetSymbolAddress((void**)&w2tp,  g_w2t);
    cudaGetSymbolAddress((void**)&w3gp,  g_w3g);
    cudaGetSymbolAddress((void**)&wr1gp, g_wr1g);
    cudaGetSymbolAddress((void**)&wr2gp, g_wr2g);

    // conv1 + weight-prep fused (prep is the 17th y-slice)
    k_conv1<<<dim3(128, 17), 128>>>(cond, w1, b1, w2, w3, r1w1, r2w1, cbk);
    k_conv2<<<dim3(8, 8, 16), 128>>>(w2tp, b2);
    // conv3: h2 already relu'd -> RELU_IN=false; writes raw h3 only
    k_c3w<true, false><<<dim3(8, 8, 16), 128>>>(h2p, w3gp, b3, h3p, 128, 128, 128, 1);

    // res-block 1: 3x3 reads raw h3 with in-loop relu; 1x1 updates h3 in place
    k_c3w<false, true><<<dim3(8, 2, 64), 128>>>(h3p, wr1gp, nullptr, tp, 32, 128, 32, 4);
    k_res1x1_add<<<dim3(64, 2, 16), 64>>>(r1w2, r1b2, r1b1);

    // res-block 2: same; 1x1 fused with pre-VQ projection
    k_c3w<false, true><<<dim3(8, 2, 64), 128>>>(h3p, wr2gp, nullptr, tp, 32, 128, 32, 4);
    k_res1x1z<<<dim3(64, 16), 64>>>(r2w2, r2b2, r2b1, wpre, bpre);

    k_vq<<<dim3(16, 16), 256>>>(cbk, (float*)d_out);
}